// round 4
// baseline (speedup 1.0000x reference)
#include <cuda_runtime.h>
#include <cstdint>

#define N_BOX 16384
#define FEAT 512
#define NUM_CATS 65
#define KSEL 25
#define MAX_DETS 1000
#define NMS_THRESH 0.6f
#define MIN_RPN 0.9f
#define MIN_AREA 220.0f
#define FLAG_WORDS 512      /* 16384/32 */
#define CAP 4096            /* max boxes passing score gate (M~1638, >60 sigma margin) */
#define NTHR 512

// Dynamic shared carve:
//   float4 sBox [CAP]  : 65536 B
//   float  sArea[CAP]  : 16384 B
//   int    sIdx [CAP]  : 16384 B
//   u64    sKeys[CAP]  : 32768 B
//   total              : 131072 B
#define DYN_BYTES (CAP * 24 + CAP * 8)

__global__ __launch_bounds__(NTHR, 1)
void kFused(const float* __restrict__ roi_boxes,
            const float* __restrict__ roi_scores,
            const float* __restrict__ det_boxes,
            const float* __restrict__ vis,
            const float* __restrict__ img_info,
            const float* __restrict__ txt,
            float* __restrict__ out) {
    extern __shared__ unsigned char dynbuf[];
    float4* sBox  = (float4*)dynbuf;
    float*  sArea = (float*)(dynbuf + CAP * 16);
    int*    sIdx  = (int*)  (dynbuf + CAP * 20);
    unsigned long long* sKeys = (unsigned long long*)(dynbuf + CAP * 24);

    __shared__ unsigned s_removed[CAP / 32];
    __shared__ unsigned s_keepw[CAP / 32];
    __shared__ unsigned s_flags[FLAG_WORDS];
    __shared__ int      s_scan[FLAG_WORDS];
    __shared__ unsigned s_row[32];
    __shared__ int      s_kept[32];
    __shared__ int      s_cnt;     // compaction counter
    __shared__ int      s_nms;     // NMS kept count (cap 1000)
    __shared__ unsigned s_km;
    __shared__ int      s_nk;
    __shared__ int      s_count;
    __shared__ int      s_selidx[KSEL];
    __shared__ float    S[KSEL][NUM_CATS];
    __shared__ float    s_key[KSEL];
    __shared__ int      s_src[KSEL];
    __shared__ unsigned char s_fgv[KSEL];

    const int tid  = threadIdx.x;
    const int lane = tid & 31;
    const int wid  = tid >> 5;       // 16 warps

    if (tid == 0) { s_cnt = 0; s_nms = 0; }
    for (int t = tid; t < CAP / 32; t += NTHR) { s_removed[t] = 0; s_keepw[t] = 0; }
    for (int t = tid; t < FLAG_WORDS; t += NTHR) s_flags[t] = 0;
    __syncthreads();

    // ---- compact boxes with score >= 0.9 (order fixed by sort below) ----
    for (int i = tid; i < N_BOX; i += NTHR) {
        float s = roi_scores[i];
        if (s >= MIN_RPN) {
            int p = atomicAdd(&s_cnt, 1);
            if (p < CAP)
                sKeys[p] = ((unsigned long long)(0xFFFFFFFFu - __float_as_uint(s)) << 32)
                           | (unsigned)i;
        }
    }
    __syncthreads();
    const int M = min(s_cnt, CAP);
    int P = 2; while (P < M) P <<= 1;

    for (int t = M + tid; t < P; t += NTHR) sKeys[t] = 0xFFFFFFFFFFFFFFFFULL;
    __syncthreads();

    // ---- bitonic sort: score desc, index asc ----
    for (int k = 2; k <= P; k <<= 1) {
        for (int j = k >> 1; j > 0; j >>= 1) {
            for (int t = tid; t < P; t += NTHR) {
                int ixj = t ^ j;
                if (ixj > t) {
                    bool up = ((t & k) == 0);
                    unsigned long long a = sKeys[t], b = sKeys[ixj];
                    if ((a > b) == up) { sKeys[t] = b; sKeys[ixj] = a; }
                }
            }
            __syncthreads();
        }
    }

    for (int t = tid; t < M; t += NTHR) {
        int orig = (int)(sKeys[t] & 0xFFFFFFFFu);
        sIdx[t] = orig;
        float4 b = ((const float4*)det_boxes)[orig];     // [y1, x1, y2, x2]
        sBox[t] = b;
        sArea[t] = (b.w - b.y) * (b.z - b.x);            // (x2-x1)*(y2-y1)
    }
    __syncthreads();

    const int Mw = (M + 31) >> 5;

    // ---- chunked greedy NMS, all operands in shared ----
    for (int c = 0; c < Mw; ++c) {
        if (s_nms >= MAX_DETS) break;                    // uniform (shared after sync)
        const int base = c * 32;
        const int lim  = min(32, M - base);

        // intra-chunk 32x32 suppression matrix: warp w does rows w and w+16
        #pragma unroll
        for (int rr = 0; rr < 2; ++rr) {
            int i = wid + rr * 16;
            unsigned bit = 0;
            if (i < lim && lane < lim && lane > i) {
                float4 bi = sBox[base + i];
                float4 bj = sBox[base + lane];
                float iw = fmaxf(0.0f, fminf(bi.w, bj.w) - fmaxf(bi.y, bj.y));
                float ih = fmaxf(0.0f, fminf(bi.z, bj.z) - fmaxf(bi.x, bj.x));
                float inter = iw * ih;
                float iou = inter / (sArea[base + i] + sArea[base + lane] - inter + 1e-12f);
                bit = (iou > NMS_THRESH) ? 1u : 0u;
            }
            unsigned row = __ballot_sync(0xffffffff, bit);
            if (lane == 0) s_row[i] = row;
        }
        __syncthreads();

        // serial greedy resolve entirely in registers (thread 0)
        if (tid == 0) {
            unsigned mrow[32];
            #pragma unroll
            for (int i = 0; i < 32; ++i) mrow[i] = s_row[i];
            unsigned rem = s_removed[c];
            unsigned km = 0;
            int cnt = s_nms, nk = 0;
            #pragma unroll
            for (int i = 0; i < 32; ++i) {
                if (i < lim && cnt < MAX_DETS && !((rem >> i) & 1u)) {
                    km |= 1u << i;
                    s_kept[nk++] = base + i;
                    ++cnt;
                    rem |= mrow[i];                      // intra-chunk suppression (j>i bits)
                }
            }
            s_keepw[c] = km;
            s_km = km;
            s_nk = nk;
            s_nms = cnt;
        }
        __syncthreads();

        // cross-chunk suppression: on-the-fly IoU of later boxes vs kept boxes
        const unsigned km = s_km;                        // uniform
        if (km) {
            const int nk = s_nk;
            for (int w = c + 1 + wid; w < Mw; w += 16) {
                int j = w * 32 + lane;
                bool sup = false;
                if (j < M) {
                    float4 bj = sBox[j];
                    float aj = sArea[j];
                    for (int k2 = 0; k2 < nk; ++k2) {
                        int ii = s_kept[k2];
                        float4 bi = sBox[ii];
                        float iw = fmaxf(0.0f, fminf(bi.w, bj.w) - fmaxf(bi.y, bj.y));
                        float ih = fmaxf(0.0f, fminf(bi.z, bj.z) - fmaxf(bi.x, bj.x));
                        float inter = iw * ih;
                        float iou = inter / (sArea[ii] + aj - inter + 1e-12f);
                        sup |= (iou > NMS_THRESH);
                    }
                }
                unsigned bal = __ballot_sync(0xffffffff, sup);
                if (lane == 0 && bal) s_removed[w] |= bal;   // warp-exclusive word
            }
        }
        __syncthreads();
    }

    // ---- valid flags on ORIGINAL indices (keep & rpn & area & nonzero roi) ----
    const float sy = img_info[4];    // image_info[2][0]
    const float sx = img_info[5];    // image_info[2][1]
    for (int t = tid; t < M; t += NTHR) {
        if ((s_keepw[t >> 5] >> (t & 31)) & 1u) {
            int orig = sIdx[t];
            float4 rb = ((const float4*)roi_boxes)[orig];
            bool allz = (rb.x == 0.f && rb.y == 0.f && rb.z == 0.f && rb.w == 0.f);
            float4 db = sBox[t];
            float area = (db.z / sy - db.x / sy) * (db.w / sx - db.y / sx);
            if (!allz && area > MIN_AREA)
                atomicOr(&s_flags[orig >> 5], 1u << (orig & 31));
        }
    }
    __syncthreads();

    // ---- first 25 valid indices, ascending original order (prefix scan) ----
    s_scan[tid] = __popc(s_flags[tid]);
    __syncthreads();
    for (int off = 1; off < FLAG_WORDS; off <<= 1) {
        int v = (tid >= off) ? s_scan[tid - off] : 0;
        __syncthreads();
        s_scan[tid] += v;
        __syncthreads();
    }
    if (tid < KSEL) s_selidx[tid] = 0;                   // jnp.nonzero fill_value = 0
    if (tid == 0) s_count = s_scan[FLAG_WORDS - 1];
    __syncthreads();
    {
        int excl = s_scan[tid] - __popc(s_flags[tid]);
        if (excl < KSEL) {
            unsigned f = s_flags[tid];
            int r = excl;
            while (f && r < KSEL) {
                int b = __ffs(f) - 1; f &= f - 1;
                s_selidx[r] = tid * 32 + b;
                ++r;
            }
        }
    }
    __syncthreads();

    // ---- GEMM: S[25][65] = vis[idx] @ txt^T ----
    for (int p = tid; p < KSEL * NUM_CATS; p += NTHR) {
        int r = p / NUM_CATS, cc = p - r * NUM_CATS;
        const float4* vf = (const float4*)(vis + (size_t)s_selidx[r] * FEAT);
        const float4* tf = (const float4*)(txt + (size_t)cc * FEAT);
        float acc = 0.f;
        #pragma unroll 8
        for (int q = 0; q < FEAT / 4; ++q) {
            float4 a = vf[q], b = tf[q];
            acc += a.x * b.x + a.y * b.y + a.z * b.z + a.w * b.w;
        }
        S[r][cc] = acc;
    }
    __syncthreads();

    // ---- per-row max / argmax, fg, sort key ----
    if (tid < KSEL) {
        float mx = S[tid][0]; int am = 0;
        for (int cc = 1; cc < NUM_CATS; ++cc) {
            float v = S[tid][cc];
            if (v > mx) { mx = v; am = cc; }             // first-occurrence argmax
        }
        bool rv = tid < min(s_count, KSEL);
        bool fg = rv && (am != 0);
        s_fgv[tid] = fg ? 1 : 0;
        s_key[tid] = fg ? mx : __int_as_float(0xff800000);   // -inf
    }
    __syncthreads();

    // ---- stable descending argsort via rank (ties -> index ascending) ----
    if (tid < KSEL) {
        float k = s_key[tid];
        int rank = 0;
        for (int j = 0; j < KSEL; ++j) {
            float kj = s_key[j];
            if (kj > k || (kj == k && j < tid)) ++rank;
        }
        s_src[rank] = tid;
    }
    __syncthreads();

    // ---- outputs: scores (25x64) | bboxes (25x4) | mask (25) ----
    for (int p = tid; p < KSEL * (NUM_CATS - 1); p += NTHR) {
        int row = p / (NUM_CATS - 1), cc = p - row * (NUM_CATS - 1);
        int s = s_src[row];
        out[p] = s_fgv[s] ? S[s][cc + 1] : 0.f;
    }
    if (tid < KSEL) {
        int s = s_src[tid];
        bool m = s_fgv[s] != 0;
        float4 db = ((const float4*)det_boxes)[s_selidx[s]];
        float xmin = db.y / sx, ymin = db.x / sy, xmax = db.w / sx, ymax = db.z / sy;
        float* o = out + KSEL * (NUM_CATS - 1) + tid * 4;
        o[0] = m ? xmin : 0.f;
        o[1] = m ? ymin : 0.f;
        o[2] = m ? xmax : 0.f;
        o[3] = m ? ymax : 0.f;
        out[KSEL * (NUM_CATS - 1) + KSEL * 4 + tid] = m ? 1.f : 0.f;
    }
}

// ---------------- launch: one kernel, one block ----------------
extern "C" void kernel_launch(void* const* d_in, const int* in_sizes, int n_in,
                              void* d_out, int out_size) {
    const float* roi_boxes  = (const float*)d_in[0];
    const float* roi_scores = (const float*)d_in[1];
    const float* det_boxes  = (const float*)d_in[2];
    /* d_in[3]: detection_masks — unused by reference outputs */
    const float* vis        = (const float*)d_in[4];
    const float* img_info   = (const float*)d_in[5];
    const float* txt        = (const float*)d_in[6];
    float* out = (float*)d_out;

    static int attr_done = 0;
    if (!attr_done) {
        cudaFuncSetAttribute(kFused, cudaFuncAttributeMaxDynamicSharedMemorySize, DYN_BYTES);
        attr_done = 1;
    }
    kFused<<<1, NTHR, DYN_BYTES>>>(roi_boxes, roi_scores, det_boxes, vis, img_info, txt, out);
}

// round 5
// speedup vs baseline: 2.7930x; 2.7930x over previous
#include <cuda_runtime.h>
#include <cstdint>

#define N_BOX 16384
#define FEAT 512
#define NUM_CATS 65
#define KSEL 25
#define MAX_DETS 1000
#define NMS_THRESH 0.6f
#define MIN_RPN 0.9f
#define MIN_AREA 220.0f
#define FLAG_WORDS 512      /* 16384/32 */
#define CAP 4096            /* max boxes passing score gate (M~1638) */
#define RW  (CAP / 32)      /* 128 words per matrix row */

// ---------------- device scratch ----------------
__device__ int    g_M;
__device__ int    g_sortedIdx[CAP];
__device__ float4 g_sortedBox[CAP];
__device__ float  g_areaArr[CAP];
__device__ unsigned g_mat[(size_t)CAP * RW];   // 2 MB suppression bitmask (w > i>>5 only)

// ================= kernel 1: compact + sort + gather =================
__global__ __launch_bounds__(1024, 1)
void kPrep(const float* __restrict__ roi_scores,
           const float* __restrict__ det_boxes) {
    extern __shared__ unsigned long long sKeys[];   // CAP entries = 32 KB
    __shared__ int s_cnt;
    const int tid = threadIdx.x;
    if (tid == 0) s_cnt = 0;
    __syncthreads();

    for (int i = tid; i < N_BOX; i += 1024) {
        float s = roi_scores[i];
        if (s >= MIN_RPN) {
            int p = atomicAdd(&s_cnt, 1);
            if (p < CAP)
                sKeys[p] = ((unsigned long long)(0xFFFFFFFFu - __float_as_uint(s)) << 32)
                           | (unsigned)i;
        }
    }
    __syncthreads();
    const int M = min(s_cnt, CAP);
    int P = 2; while (P < M) P <<= 1;
    for (int t = M + tid; t < P; t += 1024) sKeys[t] = 0xFFFFFFFFFFFFFFFFULL;
    __syncthreads();

    // bitonic sort: score desc, index asc
    for (int k = 2; k <= P; k <<= 1) {
        for (int j = k >> 1; j > 0; j >>= 1) {
            for (int t = tid; t < P; t += 1024) {
                int ixj = t ^ j;
                if (ixj > t) {
                    bool up = ((t & k) == 0);
                    unsigned long long a = sKeys[t], b = sKeys[ixj];
                    if ((a > b) == up) { sKeys[t] = b; sKeys[ixj] = a; }
                }
            }
            __syncthreads();
        }
    }

    for (int t = tid; t < M; t += 1024) {
        int orig = (int)(sKeys[t] & 0xFFFFFFFFu);
        g_sortedIdx[t] = orig;
        float4 b = ((const float4*)det_boxes)[orig];   // [y1, x1, y2, x2]
        g_sortedBox[t] = b;
        g_areaArr[t] = (b.w - b.y) * (b.z - b.x);      // (x2-x1)*(y2-y1)
    }
    if (tid == 0) g_M = M;
}

// ================= kernel 2: strictly-triangular suppression bitmask =================
__global__ void kMatrix() {
    const int M  = g_M;
    const int Mw = (M + 31) >> 5;
    const int total = M * Mw;
    const int stride = gridDim.x * blockDim.x;
    for (int it = blockIdx.x * blockDim.x + threadIdx.x; it < total; it += stride) {
        int i = it / Mw;
        int w = it - i * Mw;
        if (w <= (i >> 5)) continue;        // only strictly-later words (diag done in kFinal)
        float4 bi = g_sortedBox[i];
        float  ai = g_areaArr[i];
        unsigned bits = 0;
        int j0 = w * 32;
        int jend = min(32, M - j0);
        #pragma unroll 8
        for (int jj = 0; jj < jend; ++jj) {
            float4 bj = g_sortedBox[j0 + jj];
            float iw = fmaxf(0.0f, fminf(bi.w, bj.w) - fmaxf(bi.y, bj.y));
            float ih = fmaxf(0.0f, fminf(bi.z, bj.z) - fmaxf(bi.x, bj.x));
            float inter = iw * ih;
            float iou = inter / (ai + g_areaArr[j0 + jj] - inter + 1e-12f);
            if (iou > NMS_THRESH) bits |= (1u << jj);
        }
        g_mat[(size_t)i * RW + w] = bits;
    }
}

// ================= kernel 3: scan + select + GEMM + sort + outputs =================
#define NTHR 512
// dynamic shared: sBox[CAP] (64KB) + sArea[CAP] (16KB) = 80KB
#define FIN_DYN (CAP * 16 + CAP * 4)

__global__ __launch_bounds__(NTHR, 1)
void kFinal(const float* __restrict__ roi_boxes,
            const float* __restrict__ det_boxes,
            const float* __restrict__ vis,
            const float* __restrict__ img_info,
            const float* __restrict__ txt,
            float* __restrict__ out) {
    extern __shared__ unsigned char dynbuf[];
    float4* sBox  = (float4*)dynbuf;
    float*  sArea = (float*)(dynbuf + CAP * 16);

    __shared__ unsigned s_removed[RW];
    __shared__ unsigned s_keepw[RW];
    __shared__ unsigned s_flags[FLAG_WORDS];
    __shared__ int      s_scan[FLAG_WORDS];
    __shared__ unsigned s_row[32];
    __shared__ int      s_kept[32];
    __shared__ int      s_nms, s_nk, s_count;
    __shared__ int      s_selidx[KSEL];
    __shared__ float    S[KSEL][NUM_CATS];
    __shared__ float    s_key[KSEL];
    __shared__ int      s_src[KSEL];
    __shared__ unsigned char s_fgv[KSEL];

    const int tid  = threadIdx.x;
    const int lane = tid & 31;
    const int wid  = tid >> 5;          // 16 warps
    const int M    = g_M;
    const int Mw   = (M + 31) >> 5;

    if (tid == 0) s_nms = 0;
    for (int t = tid; t < RW; t += NTHR) { s_removed[t] = 0; s_keepw[t] = 0; }
    for (int t = tid; t < FLAG_WORDS; t += NTHR) s_flags[t] = 0;
    for (int t = tid; t < M; t += NTHR) { sBox[t] = g_sortedBox[t]; sArea[t] = g_areaArr[t]; }
    __syncthreads();

    // ---- chunked greedy NMS scan ----
    for (int c = 0; c < Mw; ++c) {
        if (s_nms >= MAX_DETS) break;                    // uniform
        const int base = c * 32;
        const int lim  = min(32, M - base);

        // intra-chunk 32x32 matrix via ballot (all operands in shared)
        #pragma unroll
        for (int rr = 0; rr < 2; ++rr) {
            int i = wid + rr * 16;
            unsigned bit = 0;
            if (i < lim && lane < lim && lane > i) {
                float4 bi = sBox[base + i];
                float4 bj = sBox[base + lane];
                float iw = fmaxf(0.0f, fminf(bi.w, bj.w) - fmaxf(bi.y, bj.y));
                float ih = fmaxf(0.0f, fminf(bi.z, bj.z) - fmaxf(bi.x, bj.x));
                float inter = iw * ih;
                float iou = inter / (sArea[base + i] + sArea[base + lane] - inter + 1e-12f);
                bit = (iou > NMS_THRESH) ? 1u : 0u;
            }
            unsigned row = __ballot_sync(0xffffffff, bit);
            if (lane == 0) s_row[i] = row;
        }
        __syncthreads();

        // serial greedy resolve in registers (thread 0)
        if (tid == 0) {
            unsigned mrow[32];
            #pragma unroll
            for (int i = 0; i < 32; ++i) mrow[i] = s_row[i];
            unsigned rem = s_removed[c];
            unsigned km = 0;
            int cnt = s_nms, nk = 0;
            #pragma unroll
            for (int i = 0; i < 32; ++i) {
                if (i < lim && cnt < MAX_DETS && !((rem >> i) & 1u)) {
                    km |= 1u << i;
                    s_kept[nk++] = base + i;
                    ++cnt;
                    rem |= mrow[i];
                }
            }
            s_keepw[c] = km;
            s_nk = nk;
            s_nms = cnt;
        }
        __syncthreads();

        // cross-chunk: warp-per-word, lane-per-kept-row (batched L2 loads, MLP=32)
        const int nk = s_nk;                             // uniform
        if (nk > 0) {
            int kr = (lane < nk) ? s_kept[lane] : -1;    // row index for this lane
            for (int w = c + 1 + wid; w < Mw; w += 16) {
                unsigned v = (kr >= 0) ? g_mat[(size_t)kr * RW + w] : 0u;
                unsigned red = __reduce_or_sync(0xffffffff, v);
                if (lane == 0 && red) s_removed[w] |= red;
            }
        }
        __syncthreads();
    }

    // ---- valid flags on ORIGINAL indices ----
    const float sy = img_info[4];    // image_info[2][0]
    const float sx = img_info[5];    // image_info[2][1]
    for (int t = tid; t < M; t += NTHR) {
        if ((s_keepw[t >> 5] >> (t & 31)) & 1u) {
            int orig = g_sortedIdx[t];
            float4 rb = ((const float4*)roi_boxes)[orig];
            bool allz = (rb.x == 0.f && rb.y == 0.f && rb.z == 0.f && rb.w == 0.f);
            float4 db = sBox[t];
            float area = (db.z / sy - db.x / sy) * (db.w / sx - db.y / sx);
            if (!allz && area > MIN_AREA)
                atomicOr(&s_flags[orig >> 5], 1u << (orig & 31));
        }
    }
    __syncthreads();

    // ---- first 25 valid indices, ascending original order ----
    s_scan[tid] = __popc(s_flags[tid]);
    __syncthreads();
    for (int off = 1; off < FLAG_WORDS; off <<= 1) {
        int v = (tid >= off) ? s_scan[tid - off] : 0;
        __syncthreads();
        s_scan[tid] += v;
        __syncthreads();
    }
    if (tid < KSEL) s_selidx[tid] = 0;                   // jnp.nonzero fill_value = 0
    if (tid == 0) s_count = s_scan[FLAG_WORDS - 1];
    __syncthreads();
    {
        int excl = s_scan[tid] - __popc(s_flags[tid]);
        if (excl < KSEL) {
            unsigned f = s_flags[tid];
            int r = excl;
            while (f && r < KSEL) {
                int b = __ffs(f) - 1; f &= f - 1;
                s_selidx[r] = tid * 32 + b;
                ++r;
            }
        }
    }
    __syncthreads();

    // ---- GEMM: S[25][65] = vis[idx] @ txt^T ----
    for (int p = tid; p < KSEL * NUM_CATS; p += NTHR) {
        int r = p / NUM_CATS, cc = p - r * NUM_CATS;
        const float4* vf = (const float4*)(vis + (size_t)s_selidx[r] * FEAT);
        const float4* tf = (const float4*)(txt + (size_t)cc * FEAT);
        float acc = 0.f;
        #pragma unroll 8
        for (int q = 0; q < FEAT / 4; ++q) {
            float4 a = vf[q], b = tf[q];
            acc += a.x * b.x + a.y * b.y + a.z * b.z + a.w * b.w;
        }
        S[r][cc] = acc;
    }
    __syncthreads();

    // ---- per-row max / argmax, fg, sort key ----
    if (tid < KSEL) {
        float mx = S[tid][0]; int am = 0;
        for (int cc = 1; cc < NUM_CATS; ++cc) {
            float v = S[tid][cc];
            if (v > mx) { mx = v; am = cc; }
        }
        bool rv = tid < min(s_count, KSEL);
        bool fg = rv && (am != 0);
        s_fgv[tid] = fg ? 1 : 0;
        s_key[tid] = fg ? mx : __int_as_float(0xff800000);   // -inf
    }
    __syncthreads();

    // ---- stable descending argsort via rank ----
    if (tid < KSEL) {
        float k = s_key[tid];
        int rank = 0;
        for (int j = 0; j < KSEL; ++j) {
            float kj = s_key[j];
            if (kj > k || (kj == k && j < tid)) ++rank;
        }
        s_src[rank] = tid;
    }
    __syncthreads();

    // ---- outputs: scores (25x64) | bboxes (25x4) | mask (25) ----
    for (int p = tid; p < KSEL * (NUM_CATS - 1); p += NTHR) {
        int row = p / (NUM_CATS - 1), cc = p - row * (NUM_CATS - 1);
        int s = s_src[row];
        out[p] = s_fgv[s] ? S[s][cc + 1] : 0.f;
    }
    if (tid < KSEL) {
        int s = s_src[tid];
        bool m = s_fgv[s] != 0;
        float4 db = ((const float4*)det_boxes)[s_selidx[s]];
        float xmin = db.y / sx, ymin = db.x / sy, xmax = db.w / sx, ymax = db.z / sy;
        float* o = out + KSEL * (NUM_CATS - 1) + tid * 4;
        o[0] = m ? xmin : 0.f;
        o[1] = m ? ymin : 0.f;
        o[2] = m ? xmax : 0.f;
        o[3] = m ? ymax : 0.f;
        out[KSEL * (NUM_CATS - 1) + KSEL * 4 + tid] = m ? 1.f : 0.f;
    }
}

// ---------------- launch ----------------
extern "C" void kernel_launch(void* const* d_in, const int* in_sizes, int n_in,
                              void* d_out, int out_size) {
    const float* roi_boxes  = (const float*)d_in[0];
    const float* roi_scores = (const float*)d_in[1];
    const float* det_boxes  = (const float*)d_in[2];
    /* d_in[3]: detection_masks — unused by reference outputs */
    const float* vis        = (const float*)d_in[4];
    const float* img_info   = (const float*)d_in[5];
    const float* txt        = (const float*)d_in[6];
    float* out = (float*)d_out;

    static int attr_done = 0;
    if (!attr_done) {
        cudaFuncSetAttribute(kPrep,  cudaFuncAttributeMaxDynamicSharedMemorySize, CAP * 8);
        cudaFuncSetAttribute(kFinal, cudaFuncAttributeMaxDynamicSharedMemorySize, FIN_DYN);
        attr_done = 1;
    }
    kPrep<<<1, 1024, CAP * 8>>>(roi_scores, det_boxes);
    kMatrix<<<512, 256>>>();
    kFinal<<<1, NTHR, FIN_DYN>>>(roi_boxes, det_boxes, vis, img_info, txt, out);
}

// round 6
// speedup vs baseline: 4.3782x; 1.5676x over previous
#include <cuda_runtime.h>
#include <cstdint>

#define N_BOX 16384
#define FEAT 512
#define NUM_CATS 65
#define KSEL 25
#define MAX_DETS 1000
#define NMS_THRESH 0.6f
#define MIN_RPN 0.9f
#define MIN_AREA 220.0f
#define FLAG_WORDS 512      /* 16384/32 */
#define CAP 4096            /* max boxes passing score gate (M~1638) */
#define RW  (CAP / 32)      /* 128 words per matrix row */

// ---------------- device scratch ----------------
__device__ int    g_M;
__device__ int    g_sortedIdx[CAP];
__device__ float4 g_sortedBox[CAP];
__device__ float  g_areaArr[CAP];
__device__ unsigned g_mat[(size_t)CAP * RW];   // 2 MB suppression bitmask (w > i>>5 only)

// ================= kernel 1: compact + sort + gather =================
__global__ __launch_bounds__(1024, 1)
void kPrep(const float* __restrict__ roi_scores,
           const float* __restrict__ det_boxes) {
    extern __shared__ unsigned long long sKeys[];   // CAP entries = 32 KB
    __shared__ int s_cnt;
    const int tid = threadIdx.x;
    if (tid == 0) s_cnt = 0;
    __syncthreads();

    for (int i = tid; i < N_BOX; i += 1024) {
        float s = roi_scores[i];
        if (s >= MIN_RPN) {
            int p = atomicAdd(&s_cnt, 1);
            if (p < CAP)
                sKeys[p] = ((unsigned long long)(0xFFFFFFFFu - __float_as_uint(s)) << 32)
                           | (unsigned)i;
        }
    }
    __syncthreads();
    const int M = min(s_cnt, CAP);
    int P = 2; while (P < M) P <<= 1;
    for (int t = M + tid; t < P; t += 1024) sKeys[t] = 0xFFFFFFFFFFFFFFFFULL;
    __syncthreads();

    // bitonic sort: score desc, index asc
    for (int k = 2; k <= P; k <<= 1) {
        for (int j = k >> 1; j > 0; j >>= 1) {
            for (int t = tid; t < P; t += 1024) {
                int ixj = t ^ j;
                if (ixj > t) {
                    bool up = ((t & k) == 0);
                    unsigned long long a = sKeys[t], b = sKeys[ixj];
                    if ((a > b) == up) { sKeys[t] = b; sKeys[ixj] = a; }
                }
            }
            __syncthreads();
        }
    }

    for (int t = tid; t < M; t += 1024) {
        int orig = (int)(sKeys[t] & 0xFFFFFFFFu);
        g_sortedIdx[t] = orig;
        float4 b = ((const float4*)det_boxes)[orig];   // [y1, x1, y2, x2]
        g_sortedBox[t] = b;
        g_areaArr[t] = (b.w - b.y) * (b.z - b.x);      // (x2-x1)*(y2-y1)
    }
    if (tid == 0) g_M = M;
}

// ================= kernel 2: strictly-triangular suppression bitmask =================
__global__ void kMatrix() {
    const int M  = g_M;
    const int Mw = (M + 31) >> 5;
    const int total = M * Mw;
    const int stride = gridDim.x * blockDim.x;
    for (int it = blockIdx.x * blockDim.x + threadIdx.x; it < total; it += stride) {
        int i = it / Mw;
        int w = it - i * Mw;
        if (w <= (i >> 5)) continue;        // only strictly-later words (diag done in kFinal)
        float4 bi = g_sortedBox[i];
        float  ai = g_areaArr[i];
        unsigned bits = 0;
        int j0 = w * 32;
        int jend = min(32, M - j0);
        #pragma unroll 8
        for (int jj = 0; jj < jend; ++jj) {
            float4 bj = g_sortedBox[j0 + jj];
            float iw = fmaxf(0.0f, fminf(bi.w, bj.w) - fmaxf(bi.y, bj.y));
            float ih = fmaxf(0.0f, fminf(bi.z, bj.z) - fmaxf(bi.x, bj.x));
            float inter = iw * ih;
            float iou = inter / (ai + g_areaArr[j0 + jj] - inter + 1e-12f);
            if (iou > NMS_THRESH) bits |= (1u << jj);
        }
        g_mat[(size_t)i * RW + w] = bits;
    }
}

// ================= kernel 3: scan + select + GEMM + sort + outputs =================
#define NTHR 512
// dynamic shared: sBox[CAP] (64KB) + sArea[CAP] (16KB) = 80KB
#define FIN_DYN (CAP * 16 + CAP * 4)

__global__ __launch_bounds__(NTHR, 1)
void kFinal(const float* __restrict__ roi_boxes,
            const float* __restrict__ det_boxes,
            const float* __restrict__ vis,
            const float* __restrict__ img_info,
            const float* __restrict__ txt,
            float* __restrict__ out) {
    extern __shared__ unsigned char dynbuf[];
    float4* sBox  = (float4*)dynbuf;
    float*  sArea = (float*)(dynbuf + CAP * 16);

    __shared__ unsigned s_removed[RW];
    __shared__ unsigned s_keepw[RW];
    __shared__ unsigned s_flags[FLAG_WORDS];
    __shared__ int      s_scan[FLAG_WORDS];
    __shared__ int      s_wsum[16];
    __shared__ unsigned s_row[32];
    __shared__ int      s_kept[32];
    __shared__ int      s_nms, s_nk, s_count;
    __shared__ int      s_selidx[KSEL];
    __shared__ float    S[KSEL][NUM_CATS];
    __shared__ float    s_key[KSEL];
    __shared__ int      s_src[KSEL];
    __shared__ unsigned char s_fgv[KSEL];

    const int tid  = threadIdx.x;
    const int lane = tid & 31;
    const int wid  = tid >> 5;          // 16 warps
    const int M    = g_M;
    const int Mw   = (M + 31) >> 5;

    if (tid == 0) s_nms = 0;
    for (int t = tid; t < RW; t += NTHR) { s_removed[t] = 0; s_keepw[t] = 0; }
    for (int t = tid; t < FLAG_WORDS; t += NTHR) s_flags[t] = 0;
    for (int t = tid; t < M; t += NTHR) { sBox[t] = g_sortedBox[t]; sArea[t] = g_areaArr[t]; }
    __syncthreads();

    // ---- chunked greedy NMS scan ----
    for (int c = 0; c < Mw; ++c) {
        if (s_nms >= MAX_DETS) break;                    // uniform
        const int base = c * 32;
        const int lim  = min(32, M - base);

        // intra-chunk 32x32 matrix via ballot (all operands in shared)
        #pragma unroll
        for (int rr = 0; rr < 2; ++rr) {
            int i = wid + rr * 16;
            unsigned bit = 0;
            if (i < lim && lane < lim && lane > i) {
                float4 bi = sBox[base + i];
                float4 bj = sBox[base + lane];
                float iw = fmaxf(0.0f, fminf(bi.w, bj.w) - fmaxf(bi.y, bj.y));
                float ih = fmaxf(0.0f, fminf(bi.z, bj.z) - fmaxf(bi.x, bj.x));
                float inter = iw * ih;
                float iou = inter / (sArea[base + i] + sArea[base + lane] - inter + 1e-12f);
                bit = (iou > NMS_THRESH) ? 1u : 0u;
            }
            unsigned row = __ballot_sync(0xffffffff, bit);
            if (lane == 0) s_row[i] = row;
        }
        __syncthreads();

        // serial greedy resolve in registers (thread 0)
        if (tid == 0) {
            unsigned mrow[32];
            #pragma unroll
            for (int i = 0; i < 32; ++i) mrow[i] = s_row[i];
            unsigned rem = s_removed[c];
            unsigned km = 0;
            int cnt = s_nms, nk = 0;
            #pragma unroll
            for (int i = 0; i < 32; ++i) {
                if (i < lim && cnt < MAX_DETS && !((rem >> i) & 1u)) {
                    km |= 1u << i;
                    s_kept[nk++] = base + i;
                    ++cnt;
                    rem |= mrow[i];
                }
            }
            s_keepw[c] = km;
            s_nk = nk;
            s_nms = cnt;
        }
        __syncthreads();

        // cross-chunk: warp-per-word, lane-per-kept-row (batched L2 loads, MLP=32)
        const int nk = s_nk;                             // uniform
        if (nk > 0) {
            int kr = (lane < nk) ? s_kept[lane] : -1;    // row index for this lane
            for (int w = c + 1 + wid; w < Mw; w += 16) {
                unsigned v = (kr >= 0) ? g_mat[(size_t)kr * RW + w] : 0u;
                unsigned red = __reduce_or_sync(0xffffffff, v);
                if (lane == 0 && red) s_removed[w] |= red;
            }
        }
        __syncthreads();
    }

    // ---- valid flags on ORIGINAL indices ----
    const float sy = img_info[4];    // image_info[2][0]
    const float sx = img_info[5];    // image_info[2][1]
    for (int t = tid; t < M; t += NTHR) {
        if ((s_keepw[t >> 5] >> (t & 31)) & 1u) {
            int orig = g_sortedIdx[t];
            float4 rb = ((const float4*)roi_boxes)[orig];
            bool allz = (rb.x == 0.f && rb.y == 0.f && rb.z == 0.f && rb.w == 0.f);
            float4 db = sBox[t];
            float area = (db.z / sy - db.x / sy) * (db.w / sx - db.y / sx);
            if (!allz && area > MIN_AREA)
                atomicOr(&s_flags[orig >> 5], 1u << (orig & 31));
        }
    }
    __syncthreads();

    // ---- inclusive prefix scan over 512 popcounts (warp shuffles, 2 barriers) ----
    {
        int v = __popc(s_flags[tid]);
        #pragma unroll
        for (int off = 1; off < 32; off <<= 1) {
            int n = __shfl_up_sync(0xffffffff, v, off);
            if (lane >= off) v += n;
        }
        if (lane == 31) s_wsum[wid] = v;
        __syncthreads();
        if (wid == 0 && lane < 16) {
            int w = s_wsum[lane];
            #pragma unroll
            for (int off = 1; off < 16; off <<= 1) {
                int n = __shfl_up_sync(0x0000ffff, w, off);
                if (lane >= off) w += n;
            }
            s_wsum[lane] = w;
        }
        __syncthreads();
        int basew = (wid > 0) ? s_wsum[wid - 1] : 0;
        s_scan[tid] = basew + v;                         // inclusive
        if (tid == 0) s_count = s_wsum[15];
    }
    if (tid < KSEL) s_selidx[tid] = 0;                   // jnp.nonzero fill_value = 0
    __syncthreads();
    {
        int excl = s_scan[tid] - __popc(s_flags[tid]);
        if (excl < KSEL) {
            unsigned f = s_flags[tid];
            int r = excl;
            while (f && r < KSEL) {
                int b = __ffs(f) - 1; f &= f - 1;
                s_selidx[r] = tid * 32 + b;
                ++r;
            }
        }
    }
    __syncthreads();

    // ---- GEMM: S[25][65] = vis[idx] @ txt^T  (warp-per-2-rows, K split across lanes) ----
    if (wid < 13) {
        const int r0 = 2 * wid;
        const int r1 = r0 + 1;
        const bool has1 = (r1 < KSEL);
        const float4* v0 = (const float4*)(vis + (size_t)s_selidx[r0] * FEAT);
        const float4* v1 = (const float4*)(vis + (size_t)s_selidx[has1 ? r1 : r0] * FEAT);
        float4 a0[4], a1[4];
        #pragma unroll
        for (int q = 0; q < 4; ++q) {
            a0[q] = v0[q * 32 + lane];                   // coalesced: 32 lanes = 512B
            a1[q] = v1[q * 32 + lane];
        }
        for (int cc = 0; cc < NUM_CATS; ++cc) {
            const float4* tf = (const float4*)(txt + (size_t)cc * FEAT);
            float p0 = 0.f, p1 = 0.f;
            #pragma unroll
            for (int q = 0; q < 4; ++q) {
                float4 b = tf[q * 32 + lane];            // coalesced
                p0 += a0[q].x * b.x + a0[q].y * b.y + a0[q].z * b.z + a0[q].w * b.w;
                p1 += a1[q].x * b.x + a1[q].y * b.y + a1[q].z * b.z + a1[q].w * b.w;
            }
            #pragma unroll
            for (int off = 16; off; off >>= 1) {
                p0 += __shfl_xor_sync(0xffffffff, p0, off);
                p1 += __shfl_xor_sync(0xffffffff, p1, off);
            }
            if (lane == 0) {
                S[r0][cc] = p0;
                if (has1) S[r1][cc] = p1;
            }
        }
    }
    __syncthreads();

    // ---- per-row max / argmax, fg, sort key ----
    if (tid < KSEL) {
        float mx = S[tid][0]; int am = 0;
        for (int cc = 1; cc < NUM_CATS; ++cc) {
            float v = S[tid][cc];
            if (v > mx) { mx = v; am = cc; }
        }
        bool rv = tid < min(s_count, KSEL);
        bool fg = rv && (am != 0);
        s_fgv[tid] = fg ? 1 : 0;
        s_key[tid] = fg ? mx : __int_as_float(0xff800000);   // -inf
    }
    __syncthreads();

    // ---- stable descending argsort via rank ----
    if (tid < KSEL) {
        float k = s_key[tid];
        int rank = 0;
        for (int j = 0; j < KSEL; ++j) {
            float kj = s_key[j];
            if (kj > k || (kj == k && j < tid)) ++rank;
        }
        s_src[rank] = tid;
    }
    __syncthreads();

    // ---- outputs: scores (25x64) | bboxes (25x4) | mask (25) ----
    for (int p = tid; p < KSEL * (NUM_CATS - 1); p += NTHR) {
        int row = p / (NUM_CATS - 1), cc = p - row * (NUM_CATS - 1);
        int s = s_src[row];
        out[p] = s_fgv[s] ? S[s][cc + 1] : 0.f;
    }
    if (tid < KSEL) {
        int s = s_src[tid];
        bool m = s_fgv[s] != 0;
        float4 db = ((const float4*)det_boxes)[s_selidx[s]];
        float xmin = db.y / sx, ymin = db.x / sy, xmax = db.w / sx, ymax = db.z / sy;
        float* o = out + KSEL * (NUM_CATS - 1) + tid * 4;
        o[0] = m ? xmin : 0.f;
        o[1] = m ? ymin : 0.f;
        o[2] = m ? xmax : 0.f;
        o[3] = m ? ymax : 0.f;
        out[KSEL * (NUM_CATS - 1) + KSEL * 4 + tid] = m ? 1.f : 0.f;
    }
}

// ---------------- launch ----------------
extern "C" void kernel_launch(void* const* d_in, const int* in_sizes, int n_in,
                              void* d_out, int out_size) {
    const float* roi_boxes  = (const float*)d_in[0];
    const float* roi_scores = (const float*)d_in[1];
    const float* det_boxes  = (const float*)d_in[2];
    /* d_in[3]: detection_masks — unused by reference outputs */
    const float* vis        = (const float*)d_in[4];
    const float* img_info   = (const float*)d_in[5];
    const float* txt        = (const float*)d_in[6];
    float* out = (float*)d_out;

    static int attr_done = 0;
    if (!attr_done) {
        cudaFuncSetAttribute(kPrep,  cudaFuncAttributeMaxDynamicSharedMemorySize, CAP * 8);
        cudaFuncSetAttribute(kFinal, cudaFuncAttributeMaxDynamicSharedMemorySize, FIN_DYN);
        attr_done = 1;
    }
    kPrep<<<1, 1024, CAP * 8>>>(roi_scores, det_boxes);
    kMatrix<<<512, 256>>>();
    kFinal<<<1, NTHR, FIN_DYN>>>(roi_boxes, det_boxes, vis, img_info, txt, out);
}